// round 11
// baseline (speedup 1.0000x reference)
#include <cuda_runtime.h>
#include <cuda_bf16.h>
#include <cuda_fp16.h>

// ---------------------------------------------------------------------------
// PointerNet additive attention, B=4, Te=Td=512, E=256, D+E=512, H=64.
// out[b,d,t] = softmax_t( sum_h w2[h]*tanh(dec_t[b,d,h] + ctx_t[b,t,h]) )
// (b2 cancels in softmax.)
//
// Kernel A: projections (R4-proven): half-warps own adjacent e-subranges,
//           lane owns an h-quad; shfl + smem reduce. ctx output TRANSPOSED
//           [b][h][t] for coalesced kernel-B reads.
// Kernel B: f16x2-packed tanh hot loop: args in f32, packed via
//           cvt.rn.f16x2.f32 (F2FP, fma-pipe), tanh.approx.f16x2 = ONE MUFU
//           per TWO elements (halves the MUFU floor), w2 pre-packed f16x2
//           (scaled by log2e), chunk-of-4 f16 accumulation flushed to f32.
//           296 blocks x 512 threads = 2 blocks/SM.
// ---------------------------------------------------------------------------

#define B_   4
#define TE_  512
#define TD_  512
#define H_   64

#define LOG2E 1.4426950408889634f

// scratch (device globals: allocation-free)
__device__ float g_ctxT[B_ * H_ * TE_];   // [b][h][t]
__device__ float g_decS[B_ * TD_ * H_];   // [b*Td+d][h]

// ---------------------------------------------------------------------------
// Kernel A: projections, 256 blocks x 256 threads, 16 rows/block.
//   blocks [0,128):   ctx rows, K=256 (e-subrange 16)
//   blocks [128,256): dec rows, K=512 (e-subrange 32)
// ---------------------------------------------------------------------------
__global__ __launch_bounds__(256) void kernelA(
    const float* __restrict__ ctx,   // [4,512,256]
    const float* __restrict__ dec,   // [4,512,512]
    const float* __restrict__ W1i,   // [256,64]
    const float* __restrict__ b1i,   // [64]
    const float* __restrict__ W1h,   // [512,64]
    const float* __restrict__ b1h)   // [64]
{
    __shared__ float buf[8192];                       // 32KB: x tile, then partials
    float4* buf4 = reinterpret_cast<float4*>(buf);

    const int tid  = threadIdx.x;
    const int wid  = tid >> 5;
    const int lane = tid & 31;
    const int hl   = (lane & 15) << 2;                // h-quad base
    const int half = lane >> 4;                       // e-subrange selector

    const bool is_ctx = (blockIdx.x < 128);
    const int  E      = is_ctx ? 256 : 512;
    const int  ESUB   = E >> 4;                       // 16 subranges
    const int  r0     = (is_ctx ? blockIdx.x : (blockIdx.x - 128)) * 16;
    const float* W    = is_ctx ? W1i : W1h;
    const float* bias = is_ctx ? b1i : b1h;
    const float* X    = is_ctx ? ctx : dec;

    // ---- load x tile [16][E] coalesced (exact tiling, no bounds) ----
    {
        const float4* src = reinterpret_cast<const float4*>(X);
        const int rowf4 = E >> 2;
        const int nf4   = 16 * rowf4;
        for (int i = tid; i < nf4; i += 256)
            buf4[i] = src[(size_t)r0 * rowf4 + i];
    }
    __syncthreads();

    // ---- mainloop ----
    float acc[16][4];
    #pragma unroll
    for (int r = 0; r < 16; r++)
        #pragma unroll
        for (int j = 0; j < 4; j++) acc[r][j] = 0.f;

    const int e0 = (wid * 2 + half) * ESUB;
    const float* wptr = W + (size_t)e0 * 64 + hl;

    #pragma unroll 1
    for (int ec = 0; ec < ESUB; ec += 4) {
        float4 w0 = *reinterpret_cast<const float4*>(wptr + (ec + 0) * 64);
        float4 w1 = *reinterpret_cast<const float4*>(wptr + (ec + 1) * 64);
        float4 w2v = *reinterpret_cast<const float4*>(wptr + (ec + 2) * 64);
        float4 w3 = *reinterpret_cast<const float4*>(wptr + (ec + 3) * 64);
        #pragma unroll
        for (int r = 0; r < 16; r++) {
            float4 x = *reinterpret_cast<const float4*>(&buf[r * E + e0 + ec]);
            acc[r][0] = fmaf(x.x, w0.x, acc[r][0]);
            acc[r][1] = fmaf(x.x, w0.y, acc[r][1]);
            acc[r][2] = fmaf(x.x, w0.z, acc[r][2]);
            acc[r][3] = fmaf(x.x, w0.w, acc[r][3]);
            acc[r][0] = fmaf(x.y, w1.x, acc[r][0]);
            acc[r][1] = fmaf(x.y, w1.y, acc[r][1]);
            acc[r][2] = fmaf(x.y, w1.z, acc[r][2]);
            acc[r][3] = fmaf(x.y, w1.w, acc[r][3]);
            acc[r][0] = fmaf(x.z, w2v.x, acc[r][0]);
            acc[r][1] = fmaf(x.z, w2v.y, acc[r][1]);
            acc[r][2] = fmaf(x.z, w2v.z, acc[r][2]);
            acc[r][3] = fmaf(x.z, w2v.w, acc[r][3]);
            acc[r][0] = fmaf(x.w, w3.x, acc[r][0]);
            acc[r][1] = fmaf(x.w, w3.y, acc[r][1]);
            acc[r][2] = fmaf(x.w, w3.z, acc[r][2]);
            acc[r][3] = fmaf(x.w, w3.w, acc[r][3]);
        }
    }

    // ---- combine half-warps (same h-quad, different e-subranges) ----
    #pragma unroll
    for (int r = 0; r < 16; r++)
        #pragma unroll
        for (int j = 0; j < 4; j++)
            acc[r][j] += __shfl_xor_sync(0xffffffffu, acc[r][j], 16);

    __syncthreads();                                  // x tile no longer needed
    if (half == 0) {
        #pragma unroll
        for (int r = 0; r < 16; r++)
            *reinterpret_cast<float4*>(&buf[wid * 1024 + r * 64 + hl]) =
                make_float4(acc[r][0], acc[r][1], acc[r][2], acc[r][3]);
    }
    __syncthreads();

    // ---- reduce 8 warp partials; each thread owns 4 consecutive outputs ----
    {
        const int o = tid * 4;                        // o = r*64 + h, h%4==0
        const int r = o >> 6;
        const int h = o & 63;
        float4 s = make_float4(0.f, 0.f, 0.f, 0.f);
        #pragma unroll
        for (int w = 0; w < 8; w++) {
            float4 p = *reinterpret_cast<const float4*>(&buf[w * 1024 + o]);
            s.x += p.x; s.y += p.y; s.z += p.z; s.w += p.w;
        }
        float4 bv = *reinterpret_cast<const float4*>(bias + h);
        s.x += bv.x; s.y += bv.y; s.z += bv.z; s.w += bv.w;

        const int row = r0 + r;
        if (is_ctx) {
            const int b = row >> 9, t = row & 511;
            float* dst = g_ctxT + ((size_t)(b << 6)) * 512 + t;
            dst[(h + 0) * 512] = s.x;
            dst[(h + 1) * 512] = s.y;
            dst[(h + 2) * 512] = s.z;
            dst[(h + 3) * 512] = s.w;
        } else {
            *reinterpret_cast<float4*>(&g_decS[(size_t)row * 64 + h]) = s;
        }
    }
}

// ---------------------------------------------------------------------------
// Kernel B: f16x2 tanh-score + softmax.
// grid = 296 (4 batches x 74 d-tiles of 7; last tile has 1 valid row).
// 512 threads: thread t owns encoder column t for its 7 decoder rows.
// ---------------------------------------------------------------------------
__device__ __forceinline__ float ex2_approx(float x) {
    float y; asm("ex2.approx.f32 %0, %1;" : "=f"(y) : "f"(x)); return y;
}
__device__ __forceinline__ __half2 htanh2(__half2 x) {
    __half2 y;
    asm("tanh.approx.f16x2 %0, %1;"
        : "=r"(*reinterpret_cast<unsigned*>(&y))
        : "r"(*reinterpret_cast<const unsigned*>(&x)));
    return y;
}

__global__ __launch_bounds__(512) void kernelB(
    const float* __restrict__ w2,    // [64]
    float* __restrict__ out)         // [4,512,512]
{
    __shared__ float dec_sh[7 * 64];
    __shared__ __half2 w2h_sh[32];   // (w2[2i], w2[2i+1]) * log2e
    __shared__ float red[7 * 16];
    __shared__ float inv_sh[7];

    const int tid = threadIdx.x;
    const int b   = blockIdx.x / 74;
    const int ti  = blockIdx.x % 74;
    const int d0  = ti * 7;

    // load decoder tile (zero-fill past batch end) + packed scaled w2
    if (tid < 448) {
        int r = tid >> 6;
        dec_sh[tid] = (d0 + r < 512) ? g_decS[((size_t)(b << 9) + d0) * 64 + tid] : 0.f;
    } else if (tid < 480) {
        int i = tid - 448;
        w2h_sh[i] = __floats2half2_rn(w2[2 * i] * LOG2E, w2[2 * i + 1] * LOG2E);
    }
    __syncthreads();

    const int t = tid;
    const float* cptr = g_ctxT + (size_t)(b << 6) * 512 + t;

    float acc[7];
    #pragma unroll
    for (int d = 0; d < 7; d++) acc[d] = 0.f;

    // hot loop: chunk of 4 h per iter; per 4 elems/d:
    //   4 FADD + 2 F2FP + 2 MUFU(tanh.f16x2) + HMUL2 + HFMA2 + 2 F2F + 2 FADD
    #pragma unroll 1
    for (int hs = 0; hs < 64; hs += 4) {
        float c0 = cptr[(hs + 0) * 512];
        float c1 = cptr[(hs + 1) * 512];
        float c2 = cptr[(hs + 2) * 512];
        float c3 = cptr[(hs + 3) * 512];
        __half2 wA = w2h_sh[(hs >> 1) + 0];
        __half2 wB = w2h_sh[(hs >> 1) + 1];
        #pragma unroll
        for (int d = 0; d < 7; d++) {
            const float* dv = &dec_sh[d * 64 + hs];
            float2 dv01 = *reinterpret_cast<const float2*>(dv);
            float2 dv23 = *reinterpret_cast<const float2*>(dv + 2);
            __half2 s0 = __floats2half2_rn(dv01.x + c0, dv01.y + c1);
            __half2 s1 = __floats2half2_rn(dv23.x + c2, dv23.y + c3);
            __half2 t0 = htanh2(s0);
            __half2 t1 = htanh2(s1);
            __half2 p  = __hmul2(wA, t0);
            p = __hfma2(wB, t1, p);                  // chunk partial (2 adds deep)
            acc[d] += __low2float(p) + __high2float(p);
        }
    }

    // softmax over t (acc already in log2 domain via scaled w2; scores
    // bounded by sum|w2|*log2e ~ 9 => no max-shift needed)
    const int wid = tid >> 5, lane = tid & 31;
    float ex[7];
    #pragma unroll
    for (int d = 0; d < 7; d++) {
        float e = ex2_approx(acc[d]);
        ex[d] = e;
        float s = e;
        #pragma unroll
        for (int off = 16; off; off >>= 1)
            s += __shfl_xor_sync(0xffffffffu, s, off);
        if (lane == 0) red[d * 16 + wid] = s;
    }
    __syncthreads();
    if (wid < 7) {
        float v = (lane < 16) ? red[wid * 16 + lane] : 0.f;
        #pragma unroll
        for (int off = 8; off; off >>= 1)
            v += __shfl_xor_sync(0xffffffffu, v, off);
        if (lane == 0) inv_sh[wid] = 1.0f / v;
    }
    __syncthreads();
    #pragma unroll
    for (int d = 0; d < 7; d++) {
        if (d0 + d < 512)
            out[((size_t)(b << 9) + d0 + d) * 512 + t] = ex[d] * inv_sh[d];
    }
}

// ---------------------------------------------------------------------------
extern "C" void kernel_launch(void* const* d_in, const int* in_sizes, int n_in,
                              void* d_out, int out_size)
{
    const float* ctx  = (const float*)d_in[0];
    const float* dec  = (const float*)d_in[1];
    const float* W1i  = (const float*)d_in[2];
    const float* b1i  = (const float*)d_in[3];
    const float* W1h  = (const float*)d_in[4];
    const float* b1h  = (const float*)d_in[5];
    const float* w2   = (const float*)d_in[6];
    float* out = (float*)d_out;

    kernelA<<<256, 256>>>(ctx, dec, W1i, b1i, W1h, b1h);
    kernelB<<<296, 512>>>(w2, out);
}

// round 12
// speedup vs baseline: 1.0460x; 1.0460x over previous
#include <cuda_runtime.h>
#include <cuda_bf16.h>

// ---------------------------------------------------------------------------
// PointerNet additive attention, B=4, Te=Td=512, E=256, D+E=512, H=64.
// out[b,d,t] = softmax_t( sum_h w2[h]*tanh(dec_t[b,d,h] + ctx_t[b,t,h]) )
// (b2 cancels in softmax.)
//
// Kernel A: ctx projection ONLY -> g_ctxT transposed [b][h][t].
//           (dec projection moved into kernel B's producer warps.)
// Kernel B: 296 blocks x 640 threads, 7 decoder rows each.
//   warps 0-15 (512 thr): R4's measured-at-MUFU-floor tanh/softmax loop,
//                         gated per 16-h chunk on bar.sync(1+c, 640).
//   warps 16-19 (128 thr): load dec tile + dec projection in four 16-h
//                         chunks -> dec_sh, publish via bar.arrive(1+c,640).
//   The dec FMA work (5.3us chip-wide) hides entirely under the 21us MUFU
//   phase; graph edge A->B provides the ctx dependency (no flags/spins).
// ---------------------------------------------------------------------------

#define LOG2E 1.4426950408889634f

__device__ float g_ctxT[4 * 64 * 512];   // [b][h][t]

__device__ __forceinline__ float ex2_approx(float x) {
    float y; asm("ex2.approx.f32 %0, %1;" : "=f"(y) : "f"(x)); return y;
}
__device__ __forceinline__ float tanh_approx(float x) {
    float y; asm("tanh.approx.f32 %0, %1;" : "=f"(y) : "f"(x)); return y;
}
__device__ __forceinline__ void bar_sync(int id, int cnt) {
    asm volatile("bar.sync %0, %1;" :: "r"(id), "r"(cnt) : "memory");
}
__device__ __forceinline__ void bar_arrive(int id, int cnt) {
    asm volatile("bar.arrive %0, %1;" :: "r"(id), "r"(cnt) : "memory");
}

// ---------------------------------------------------------------------------
// Kernel A: ctx projection, 128 blocks x 256 threads, 16 rows/block, K=256.
// Half-warps own adjacent 16-e subranges; lane owns an h-quad.
// ---------------------------------------------------------------------------
__global__ __launch_bounds__(256) void kernelA(
    const float* __restrict__ ctx,   // [4,512,256]
    const float* __restrict__ W1i,   // [256,64]
    const float* __restrict__ b1i)   // [64]
{
    __shared__ float buf[8192];                       // x tile 4096 + partials
    float4* buf4 = reinterpret_cast<float4*>(buf);

    const int tid  = threadIdx.x;
    const int wid  = tid >> 5;
    const int lane = tid & 31;
    const int hl   = (lane & 15) << 2;                // h-quad base
    const int half = lane >> 4;                       // e-subrange selector
    const int r0   = blockIdx.x * 16;

    // ---- load x tile [16][256] coalesced ----
    for (int i = tid; i < 1024; i += 256)
        buf4[i] = reinterpret_cast<const float4*>(ctx)[(size_t)r0 * 64 + i];
    __syncthreads();

    // ---- mainloop: 16 subranges of 16 e ----
    float acc[16][4];
    #pragma unroll
    for (int r = 0; r < 16; r++)
        #pragma unroll
        for (int j = 0; j < 4; j++) acc[r][j] = 0.f;

    const int e0 = (wid * 2 + half) * 16;
    const float* wptr = W1i + (size_t)e0 * 64 + hl;

    #pragma unroll 1
    for (int ec = 0; ec < 16; ec += 4) {
        float4 w0 = *reinterpret_cast<const float4*>(wptr + (ec + 0) * 64);
        float4 w1 = *reinterpret_cast<const float4*>(wptr + (ec + 1) * 64);
        float4 w2v = *reinterpret_cast<const float4*>(wptr + (ec + 2) * 64);
        float4 w3 = *reinterpret_cast<const float4*>(wptr + (ec + 3) * 64);
        #pragma unroll
        for (int r = 0; r < 16; r++) {
            float4 x = *reinterpret_cast<const float4*>(&buf[r * 256 + e0 + ec]);
            acc[r][0] = fmaf(x.x, w0.x, acc[r][0]);
            acc[r][1] = fmaf(x.x, w0.y, acc[r][1]);
            acc[r][2] = fmaf(x.x, w0.z, acc[r][2]);
            acc[r][3] = fmaf(x.x, w0.w, acc[r][3]);
            acc[r][0] = fmaf(x.y, w1.x, acc[r][0]);
            acc[r][1] = fmaf(x.y, w1.y, acc[r][1]);
            acc[r][2] = fmaf(x.y, w1.z, acc[r][2]);
            acc[r][3] = fmaf(x.y, w1.w, acc[r][3]);
            acc[r][0] = fmaf(x.z, w2v.x, acc[r][0]);
            acc[r][1] = fmaf(x.z, w2v.y, acc[r][1]);
            acc[r][2] = fmaf(x.z, w2v.z, acc[r][2]);
            acc[r][3] = fmaf(x.z, w2v.w, acc[r][3]);
            acc[r][0] = fmaf(x.w, w3.x, acc[r][0]);
            acc[r][1] = fmaf(x.w, w3.y, acc[r][1]);
            acc[r][2] = fmaf(x.w, w3.z, acc[r][2]);
            acc[r][3] = fmaf(x.w, w3.w, acc[r][3]);
        }
    }

    // combine half-warps, reduce 8 warp partials
    #pragma unroll
    for (int r = 0; r < 16; r++)
        #pragma unroll
        for (int j = 0; j < 4; j++)
            acc[r][j] += __shfl_xor_sync(0xffffffffu, acc[r][j], 16);

    __syncthreads();
    if (half == 0) {
        #pragma unroll
        for (int r = 0; r < 16; r++)
            *reinterpret_cast<float4*>(&buf[wid * 1024 + r * 64 + hl]) =
                make_float4(acc[r][0], acc[r][1], acc[r][2], acc[r][3]);
    }
    __syncthreads();

    {
        const int o = tid * 4;
        const int r = o >> 6;
        const int h = o & 63;
        float4 s = make_float4(0.f, 0.f, 0.f, 0.f);
        #pragma unroll
        for (int w = 0; w < 8; w++) {
            float4 p = *reinterpret_cast<const float4*>(&buf[w * 1024 + o]);
            s.x += p.x; s.y += p.y; s.z += p.z; s.w += p.w;
        }
        float4 bv = *reinterpret_cast<const float4*>(b1i + h);
        s.x += bv.x; s.y += bv.y; s.z += bv.z; s.w += bv.w;

        const int row = r0 + r;
        const int bb = row >> 9, t = row & 511;
        float* dst = g_ctxT + ((size_t)(bb << 6)) * 512 + t;
        dst[(h + 0) * 512] = s.x;
        dst[(h + 1) * 512] = s.y;
        dst[(h + 2) * 512] = s.z;
        dst[(h + 3) * 512] = s.w;
    }
}

// ---------------------------------------------------------------------------
// Kernel B: tanh-score + softmax with in-kernel dec projection.
// 296 blocks x 640 threads (2 blocks/SM). 7 decoder rows per block.
// ---------------------------------------------------------------------------
__global__ __launch_bounds__(640, 2) void kernelB(
    const float* __restrict__ dec,   // [4,512,512]
    const float* __restrict__ W1h,   // [512,64]
    const float* __restrict__ b1h,   // [64]
    const float* __restrict__ w2,    // [64]
    float* __restrict__ out)         // [4,512,512]
{
    __shared__ __align__(16) float DT[7 * 512];      // dec tile
    __shared__ __align__(16) float dec_sh[7 * 64];   // projected dec
    __shared__ __align__(16) float w2_sh[64];        // pre-scaled by log2e
    __shared__ float pb[2][4 * 112];                 // producer partials
    __shared__ float red[7 * 16];
    __shared__ float inv_sh[7];

    const int tid  = threadIdx.x;
    const int wid  = tid >> 5;
    const int lane = tid & 31;
    const int b    = blockIdx.x / 74;
    const int ti   = blockIdx.x % 74;
    const int d0   = ti * 7;

    if (wid < 16) {
        // ============================ CONSUMERS =============================
        if (tid < 64) w2_sh[tid] = w2[tid] * LOG2E;

        const int t = tid;                            // 0..511
        const float* cptr = g_ctxT + (size_t)(b << 6) * 512 + t;

        float acc[7];
        #pragma unroll
        for (int d = 0; d < 7; d++) acc[d] = 0.f;

        float c0 = cptr[0 * 512];
        float c1 = cptr[1 * 512];
        float c2 = cptr[2 * 512];
        float c3 = cptr[3 * 512];

        #pragma unroll 1
        for (int c = 0; c < 4; c++) {
            bar_sync(1 + c, 640);                     // wait dec chunk c
            #pragma unroll
            for (int hh = 0; hh < 16; hh += 4) {
                const int h = (c << 4) + hh;
                const int hn = (h + 4) & 63;
                float n0 = cptr[(hn + 0) * 512];
                float n1 = cptr[(hn + 1) * 512];
                float n2 = cptr[(hn + 2) * 512];
                float n3 = cptr[(hn + 3) * 512];

                float4 w4 = *reinterpret_cast<const float4*>(&w2_sh[h]);
                #pragma unroll
                for (int d = 0; d < 7; d++) {
                    float4 dv = *reinterpret_cast<const float4*>(&dec_sh[(d << 6) + h]);
                    acc[d] = fmaf(w4.x, tanh_approx(dv.x + c0), acc[d]);
                    acc[d] = fmaf(w4.y, tanh_approx(dv.y + c1), acc[d]);
                    acc[d] = fmaf(w4.z, tanh_approx(dv.z + c2), acc[d]);
                    acc[d] = fmaf(w4.w, tanh_approx(dv.w + c3), acc[d]);
                }
                c0 = n0; c1 = n1; c2 = n2; c3 = n3;
            }
        }

        // softmax over t (acc in log2 domain via scaled w2; scores bounded
        // by sum|w2|*log2e ~ 9 => no max-shift needed)
        float ex[7];
        #pragma unroll
        for (int d = 0; d < 7; d++) {
            float e = ex2_approx(acc[d]);
            ex[d] = e;
            float s = e;
            #pragma unroll
            for (int off = 16; off; off >>= 1)
                s += __shfl_xor_sync(0xffffffffu, s, off);
            if (lane == 0) red[d * 16 + wid] = s;
        }
        bar_sync(5, 512);
        if (wid < 7) {
            float v = (lane < 16) ? red[wid * 16 + lane] : 0.f;
            #pragma unroll
            for (int off = 8; off; off >>= 1)
                v += __shfl_xor_sync(0xffffffffu, v, off);
            if (lane == 0) inv_sh[wid] = 1.0f / v;
        }
        bar_sync(5, 512);
        #pragma unroll
        for (int d = 0; d < 7; d++) {
            if (d0 + d < 512)
                out[((size_t)(b << 9) + d0 + d) * 512 + t] = ex[d] * inv_sh[d];
        }
    } else {
        // ============================ PRODUCERS =============================
        const int q     = tid - 512;                  // 0..127
        const int p     = wid - 16;                   // 0..3: e-range 128
        const int phalf = lane >> 4;                  // 64-e subrange
        const int hl    = lane & 15;                  // h within chunk

        // ---- load dec tile (zero-fill past batch end) ----
        {
            const float4* dsrc = reinterpret_cast<const float4*>(dec)
                               + ((size_t)(b << 9) + d0) * 128;
            float4* DT4 = reinterpret_cast<float4*>(DT);
            #pragma unroll
            for (int i = q; i < 896; i += 128) {
                int r = i >> 7;
                DT4[i] = (d0 + r < 512) ? dsrc[i] : make_float4(0.f,0.f,0.f,0.f);
            }
        }
        bar_sync(6, 128);

        const int e0 = p * 128 + phalf * 64;
        const float* xb = DT + e0;

        #pragma unroll 1
        for (int c = 0; c < 4; c++) {
            const int hbase = c << 4;
            float acc[7];
            #pragma unroll
            for (int r = 0; r < 7; r++) acc[r] = 0.f;

            const float* wp = W1h + (size_t)e0 * 64 + hbase + hl;
            #pragma unroll 4
            for (int ec = 0; ec < 64; ec += 4) {
                float w0 = wp[(ec + 0) * 64];
                float w1 = wp[(ec + 1) * 64];
                float w2v = wp[(ec + 2) * 64];
                float w3 = wp[(ec + 3) * 64];
                #pragma unroll
                for (int r = 0; r < 7; r++) {
                    float4 x = *reinterpret_cast<const float4*>(xb + r * 512 + ec);
                    acc[r] = fmaf(x.x, w0,
                             fmaf(x.y, w1,
                             fmaf(x.z, w2v,
                             fmaf(x.w, w3, acc[r]))));
                }
            }
            #pragma unroll
            for (int r = 0; r < 7; r++)
                acc[r] += __shfl_xor_sync(0xffffffffu, acc[r], 16);

            float* pbc = pb[c & 1];
            if (phalf == 0) {
                #pragma unroll
                for (int r = 0; r < 7; r++)
                    pbc[p * 112 + r * 16 + hl] = acc[r];
            }
            bar_sync(6, 128);
            if (q < 112) {
                const int r = q >> 4, hh = q & 15;
                float s = pbc[q] + pbc[112 + q] + pbc[224 + q] + pbc[336 + q];
                dec_sh[(r << 6) + hbase + hh] = s + b1h[hbase + hh];
            }
            bar_arrive(1 + c, 640);                   // publish chunk c
        }
        // producers exit
    }
}

// ---------------------------------------------------------------------------
extern "C" void kernel_launch(void* const* d_in, const int* in_sizes, int n_in,
                              void* d_out, int out_size)
{
    const float* ctx  = (const float*)d_in[0];
    const float* dec  = (const float*)d_in[1];
    const float* W1i  = (const float*)d_in[2];
    const float* b1i  = (const float*)d_in[3];
    const float* W1h  = (const float*)d_in[4];
    const float* b1h  = (const float*)d_in[5];
    const float* w2   = (const float*)d_in[6];
    float* out = (float*)d_out;

    kernelA<<<128, 256>>>(ctx, W1i, b1i);
    kernelB<<<296, 640>>>(dec, W1h, b1h, w2, out);
}

// round 13
// speedup vs baseline: 1.0727x; 1.0256x over previous
#include <cuda_runtime.h>
#include <cuda_bf16.h>

// ---------------------------------------------------------------------------
// PointerNet additive attention, B=4, Te=Td=512, E=256, D+E=512, H=64.
// out[b,d,t] = softmax_t( sum_h w2[h]*tanh(dec_t[b,d,h] + ctx_t[b,t,h]) )
// (b2 cancels in softmax.)
//
// Kernel A: projections using PACKED DUAL-FP32 FMA (fma.rn.f32x2 -> FFMA2),
//           which ptxas never emits from C++ -- 2 FMAs per FMA-pipe slot.
//           Lane owns an h-quad as TWO packed f32x2 accumulators; x values
//           broadcast-duplicated via mov.b64 (ALU pipe, idle). Half-warps
//           own adjacent e-subranges (shfl-combined); 8 warp partials
//           reduced through smem. ctx output TRANSPOSED [b][h][t].
//           Balanced grid: rows*E = 4096 per block (ctx 16 rows, dec 8).
// Kernel B: R4's measured-at-MUFU-floor tanh/softmax kernel, unchanged.
// ---------------------------------------------------------------------------

#define LOG2E 1.4426950408889634f

// scratch (device globals: allocation-free)
__device__ float g_ctxT[4 * 64 * 512];   // [b][h][t]
__device__ float g_decS[4 * 512 * 64];   // [b*Td+d][h]

// ---- packed f32x2 helpers ----
__device__ __forceinline__ unsigned long long pack2(float v) {
    unsigned long long r;
    asm("mov.b64 %0, {%1, %1};" : "=l"(r) : "f"(v));
    return r;
}
__device__ __forceinline__ void fma2(unsigned long long& d,
                                     unsigned long long a,
                                     unsigned long long b) {
    asm("fma.rn.f32x2 %0, %1, %2, %0;" : "+l"(d) : "l"(a), "l"(b));
}
__device__ __forceinline__ void add2(unsigned long long& d,
                                     unsigned long long a) {
    asm("add.rn.f32x2 %0, %0, %1;" : "+l"(d) : "l"(a));
}

__device__ __forceinline__ float ex2_approx(float x) {
    float y; asm("ex2.approx.f32 %0, %1;" : "=f"(y) : "f"(x)); return y;
}
__device__ __forceinline__ float tanh_approx(float x) {
    float y; asm("tanh.approx.f32 %0, %1;" : "=f"(y) : "f"(x)); return y;
}

// ---------------------------------------------------------------------------
// Kernel A mainloop, templated on rows R and depth E (R*E = 4096).
// 256 threads: 8 warps x 2 half-warps own 16 e-subranges of E/16;
// lane owns h-quad = 2 packed f32x2 accumulators per row.
// ---------------------------------------------------------------------------
template<int R, int E, bool IS_CTX>
__device__ __forceinline__ void projA(
    float* buf,                      // smem: 4096-float tile + 8192 partials
    const float* __restrict__ X,
    const float* __restrict__ W,
    const float* __restrict__ bias,
    int r0)
{
    const int tid  = threadIdx.x;
    const int wid  = tid >> 5;
    const int lane = tid & 31;
    const int hl   = (lane & 15) << 2;            // h-quad base
    const int half = lane >> 4;                   // e-subrange selector

    // ---- load x tile [R][E] coalesced (exact tiling, no bounds) ----
    {
        float4* buf4 = reinterpret_cast<float4*>(buf);
        const float4* src = reinterpret_cast<const float4*>(X)
                          + (size_t)r0 * (E >> 2);
        #pragma unroll
        for (int i = tid; i < 1024; i += 256)     // R*E/4 = 1024 always
            buf4[i] = src[i];
    }
    __syncthreads();

    // ---- mainloop: packed dual-fp32 FMA ----
    unsigned long long acc[R][2];
    #pragma unroll
    for (int r = 0; r < R; r++) { acc[r][0] = 0ull; acc[r][1] = 0ull; }

    const int ESUB = E >> 4;                      // 16 subranges
    const int e0 = (wid * 2 + half) * ESUB;
    const float* wptr = W + (size_t)e0 * 64 + hl;

    #pragma unroll 1
    for (int ec = 0; ec < ESUB; ec += 4) {
        // each ulonglong2 = two packed f32x2 pairs = one h-quad of weights
        ulonglong2 w0 = *reinterpret_cast<const ulonglong2*>(wptr + (ec + 0) * 64);
        ulonglong2 w1 = *reinterpret_cast<const ulonglong2*>(wptr + (ec + 1) * 64);
        ulonglong2 w2v = *reinterpret_cast<const ulonglong2*>(wptr + (ec + 2) * 64);
        ulonglong2 w3 = *reinterpret_cast<const ulonglong2*>(wptr + (ec + 3) * 64);
        #pragma unroll
        for (int r = 0; r < R; r++) {
            float4 x = *reinterpret_cast<const float4*>(&buf[r * E + e0 + ec]);
            unsigned long long xx;
            xx = pack2(x.x); fma2(acc[r][0], xx, w0.x); fma2(acc[r][1], xx, w0.y);
            xx = pack2(x.y); fma2(acc[r][0], xx, w1.x); fma2(acc[r][1], xx, w1.y);
            xx = pack2(x.z); fma2(acc[r][0], xx, w2v.x); fma2(acc[r][1], xx, w2v.y);
            xx = pack2(x.w); fma2(acc[r][0], xx, w3.x); fma2(acc[r][1], xx, w3.y);
        }
    }

    // ---- combine half-warps (same h-quad, different e-subranges) ----
    #pragma unroll
    for (int r = 0; r < R; r++) {
        unsigned long long o0 = __shfl_xor_sync(0xffffffffu, acc[r][0], 16);
        unsigned long long o1 = __shfl_xor_sync(0xffffffffu, acc[r][1], 16);
        add2(acc[r][0], o0);
        add2(acc[r][1], o1);
    }

    __syncthreads();                              // x tile no longer needed
    if (half == 0) {
        #pragma unroll
        for (int r = 0; r < R; r++) {
            // packed bits == float4{h0,h1,h2,h3} layout (little-endian)
            *reinterpret_cast<ulonglong2*>(&buf[wid * 1024 + r * 64 + hl]) =
                make_ulonglong2(acc[r][0], acc[r][1]);
        }
    }
    __syncthreads();

    // ---- reduce 8 warp partials; thread owns 4 consecutive outputs ----
    if (tid < R * 16) {
        const int o = tid * 4;                    // o = r*64 + h, h%4==0
        const int r = o >> 6;
        const int h = o & 63;
        float4 s = make_float4(0.f, 0.f, 0.f, 0.f);
        #pragma unroll
        for (int w = 0; w < 8; w++) {
            float4 p = *reinterpret_cast<const float4*>(&buf[w * 1024 + o]);
            s.x += p.x; s.y += p.y; s.z += p.z; s.w += p.w;
        }
        float4 bv = *reinterpret_cast<const float4*>(bias + h);
        s.x += bv.x; s.y += bv.y; s.z += bv.z; s.w += bv.w;

        const int row = r0 + r;
        if (IS_CTX) {
            const int b = row >> 9, t = row & 511;
            float* dst = g_ctxT + ((size_t)(b << 6)) * 512 + t;
            dst[(h + 0) * 512] = s.x;
            dst[(h + 1) * 512] = s.y;
            dst[(h + 2) * 512] = s.z;
            dst[(h + 3) * 512] = s.w;
        } else {
            *reinterpret_cast<float4*>(&g_decS[(size_t)row * 64 + h]) = s;
        }
    }
}

// ---------------------------------------------------------------------------
// Kernel A: 384 blocks x 256 threads.
//   blocks [0,128):   ctx, 16 rows/block, K=256
//   blocks [128,384): dec,  8 rows/block, K=512  (equal FMA work per block)
// ---------------------------------------------------------------------------
__global__ __launch_bounds__(256) void kernelA(
    const float* __restrict__ ctx,   // [4,512,256]
    const float* __restrict__ dec,   // [4,512,512]
    const float* __restrict__ W1i,   // [256,64]
    const float* __restrict__ b1i,   // [64]
    const float* __restrict__ W1h,   // [512,64]
    const float* __restrict__ b1h)   // [64]
{
    __shared__ __align__(16) float buf[8192];     // 32KB: tile + partials

    if (blockIdx.x < 128) {
        projA<16, 256, true >(buf, ctx, W1i, b1i, blockIdx.x * 16);
    } else {
        projA< 8, 512, false>(buf, dec, W1h, b1h, (blockIdx.x - 128) * 8);
    }
}

// ---------------------------------------------------------------------------
// Kernel B: fused tanh-score + softmax (R4 gold version, unchanged).
// grid = 296 (4 batches x 74 d-tiles of 7) => 2 blocks/SM.
// ---------------------------------------------------------------------------
__global__ __launch_bounds__(512) void kernelB(
    const float* __restrict__ w2,    // [64]
    float* __restrict__ out)         // [4,512,512]
{
    __shared__ float dec_sh[7 * 64];
    __shared__ float w2_sh[64];      // pre-scaled by log2(e)
    __shared__ float red[7 * 16];
    __shared__ float inv_sh[7];

    const int tid = threadIdx.x;
    const int b   = blockIdx.x / 74;
    const int ti  = blockIdx.x % 74;
    const int d0  = ti * 7;

    // load decoder tile (zero-fill past batch end) + w2*log2e
    if (tid < 448) {
        int r = tid >> 6;
        dec_sh[tid] = (d0 + r < 512) ? g_decS[((size_t)(b << 9) + d0) * 64 + tid] : 0.f;
    } else {
        w2_sh[tid - 448] = w2[tid - 448] * LOG2E;
    }
    __syncthreads();

    const float* cptr = g_ctxT + (size_t)(b << 6) * 512 + tid;

    float acc[7];
    #pragma unroll
    for (int d = 0; d < 7; d++) acc[d] = 0.f;

    // prime the pipeline with h-group 0
    float c0 = cptr[0 * 512];
    float c1 = cptr[1 * 512];
    float c2 = cptr[2 * 512];
    float c3 = cptr[3 * 512];

    #pragma unroll 1
    for (int h = 0; h < 64; h += 4) {
        // prefetch next group (wrap &63 on last iter: in-bounds, cached, unused)
        const int hn = (h + 4) & 63;
        float n0 = cptr[(hn + 0) * 512];
        float n1 = cptr[(hn + 1) * 512];
        float n2 = cptr[(hn + 2) * 512];
        float n3 = cptr[(hn + 3) * 512];

        float4 w4 = *reinterpret_cast<const float4*>(&w2_sh[h]);
        #pragma unroll
        for (int d = 0; d < 7; d++) {
            float4 dv = *reinterpret_cast<const float4*>(&dec_sh[d * 64 + h]);
            acc[d] = fmaf(w4.x, tanh_approx(dv.x + c0), acc[d]);
            acc[d] = fmaf(w4.y, tanh_approx(dv.y + c1), acc[d]);
            acc[d] = fmaf(w4.z, tanh_approx(dv.z + c2), acc[d]);
            acc[d] = fmaf(w4.w, tanh_approx(dv.w + c3), acc[d]);
        }
        c0 = n0; c1 = n1; c2 = n2; c3 = n3;
    }

    // softmax over t (acc in log2 domain; b2 cancels; scores bounded by
    // sum|w2|*log2e ~ 9 => no max-shift needed)
    const int wid = tid >> 5, lane = tid & 31;
    float ex[7];
    #pragma unroll
    for (int d = 0; d < 7; d++) {
        float e = ex2_approx(acc[d]);
        ex[d] = e;
        float s = e;
        #pragma unroll
        for (int off = 16; off; off >>= 1)
            s += __shfl_xor_sync(0xffffffffu, s, off);
        if (lane == 0) red[d * 16 + wid] = s;
    }
    __syncthreads();
    if (wid < 7) {
        float v = (lane < 16) ? red[wid * 16 + lane] : 0.f;
        #pragma unroll
        for (int off = 8; off; off >>= 1)
            v += __shfl_xor_sync(0xffffffffu, v, off);
        if (lane == 0) inv_sh[wid] = 1.0f / v;
    }
    __syncthreads();
    #pragma unroll
    for (int d = 0; d < 7; d++) {
        if (d0 + d < 512)
            out[((size_t)(b << 9) + d0 + d) * 512 + tid] = ex[d] * inv_sh[d];
    }
}

// ---------------------------------------------------------------------------
extern "C" void kernel_launch(void* const* d_in, const int* in_sizes, int n_in,
                              void* d_out, int out_size)
{
    const float* ctx  = (const float*)d_in[0];
    const float* dec  = (const float*)d_in[1];
    const float* W1i  = (const float*)d_in[2];
    const float* b1i  = (const float*)d_in[3];
    const float* W1h  = (const float*)d_in[4];
    const float* b1h  = (const float*)d_in[5];
    const float* w2   = (const float*)d_in[6];
    float* out = (float*)d_out;

    kernelA<<<384, 256>>>(ctx, dec, W1i, b1i, W1h, b1h);
    kernelB<<<296, 512>>>(w2, out);
}